// round 6
// baseline (speedup 1.0000x reference)
#include <cuda_runtime.h>
#include <cuda.h>
#include <math.h>
#include <stdint.h>

#define Bb 256
#define Dd 2048
#define Nn 65536
#define Pp 4096
#define CTOT (Pp + Nn)
#define TINV 20.0f
#define EPS_ 0.1f

#define BNg 128                  // N cols per CTA
#define NBLK (Nn / BNg)          // 512 CTAs
#define KC 32                    // K floats per stage (128 B rows)
#define NIT (Dd / KC)            // 64
#define NSTG 4
#define A_BY 32768               // 256 rows x 128 B
#define B_BY 16384               // 128 rows x 128 B
#define STG_BY (A_BY + B_BY)     // 49152
#define SMEM_DYN (NSTG * STG_BY + 1024)

__device__ __align__(128) float g_xn[Bb * Dd];
__device__ float g_M[Bb], g_szp[Bb], g_sep[Bb], g_zt[Bb], g_rowloss[Bb];
__device__ float g_psv[Bb * NBLK], g_pse[Bb * NBLK];

// ---------------- PTX helpers (all sm_90-or-older features) ----------------
__device__ __forceinline__ uint32_t cvs(const void* p) {
    return (uint32_t)__cvta_generic_to_shared(p);
}
__device__ __forceinline__ void mbar_init(uint32_t a, uint32_t c) {
    asm volatile("mbarrier.init.shared.b64 [%0], %1;" :: "r"(a), "r"(c) : "memory");
}
__device__ __forceinline__ void mbar_expect(uint32_t a, uint32_t tx) {
    asm volatile("mbarrier.arrive.expect_tx.shared.b64 _, [%0], %1;"
                 :: "r"(a), "r"(tx) : "memory");
}
__device__ __forceinline__ void mbar_arrive(uint32_t a) {
    asm volatile("mbarrier.arrive.shared.b64 _, [%0];" :: "r"(a) : "memory");
}
__device__ __forceinline__ void mbar_wait(uint32_t a, uint32_t ph) {
    asm volatile(
        "{\n\t.reg .pred P;\n\t"
        "W_%=:\n\t"
        "mbarrier.try_wait.parity.acquire.cta.shared::cta.b64 P, [%0], %1, 0x989680;\n\t"
        "@P bra D_%=;\n\t"
        "bra.uni W_%=;\n\t"
        "D_%=:\n\t}"
        :: "r"(a), "r"(ph) : "memory");
}
__device__ __forceinline__ void tma2d(uint32_t dst, const CUtensorMap* m,
                                      int x, int y, uint32_t bar) {
    asm volatile(
        "cp.async.bulk.tensor.2d.shared::cta.global.tile.mbarrier::complete_tx::bytes "
        "[%0], [%1, {%2, %3}], [%4];"
        :: "r"(dst), "l"(m), "r"(x), "r"(y), "r"(bar) : "memory");
}
__device__ __forceinline__ float lds32(uint32_t a) {
    float v;
    asm volatile("ld.shared.f32 %0, [%1];" : "=f"(v) : "r"(a));
    return v;
}
__device__ __forceinline__ void mma8(float c[4], const uint32_t a[4],
                                     uint32_t b0, uint32_t b1) {
    asm("mma.sync.aligned.m16n8k8.row.col.f32.tf32.tf32.f32 "
        "{%0,%1,%2,%3},{%4,%5,%6,%7},{%8,%9},{%0,%1,%2,%3};"
        : "+f"(c[0]), "+f"(c[1]), "+f"(c[2]), "+f"(c[3])
        : "r"(a[0]), "r"(a[1]), "r"(a[2]), "r"(a[3]), "r"(b0), "r"(b1));
}

// ---------------- K1: normalize inputs (fp32 out) ----------------
__global__ void k_normalize(const float* __restrict__ in) {
    int row = blockIdx.x, tid = threadIdx.x;
    const float4* src = (const float4*)(in + (size_t)row * Dd);
    float4 v0 = src[tid], v1 = src[tid + 256];
    float ss = v0.x*v0.x + v0.y*v0.y + v0.z*v0.z + v0.w*v0.w
             + v1.x*v1.x + v1.y*v1.y + v1.z*v1.z + v1.w*v1.w;
    #pragma unroll
    for (int o = 16; o; o >>= 1) ss += __shfl_xor_sync(~0u, ss, o);
    __shared__ float sh[8];
    if ((tid & 31) == 0) sh[tid >> 5] = ss;
    __syncthreads();
    if (tid == 0) {
        float t = 0.f;
        #pragma unroll
        for (int i = 0; i < 8; i++) t += sh[i];
        sh[0] = rsqrtf(t);
    }
    __syncthreads();
    float iv = sh[0];
    float4* dst = (float4*)(g_xn + (size_t)row * Dd);
    v0.x*=iv; v0.y*=iv; v0.z*=iv; v0.w*=iv;
    v1.x*=iv; v1.y*=iv; v1.z*=iv; v1.w*=iv;
    dst[tid] = v0; dst[tid + 256] = v1;
}

// ---------------- K2: prototype stats: M, sum z, sumexp(z-M) ----------------
__global__ void k_prep(const float* __restrict__ proto) {
    int b = blockIdx.x, tid = threadIdx.x;
    const float4* pr = (const float4*)(proto + (size_t)b * Pp);
    float mx = -1e30f, sm = 0.f;
    #pragma unroll 4
    for (int i = tid; i < Pp / 4; i += 256) {
        float4 v = pr[i];
        sm += (v.x + v.y) + (v.z + v.w);
        mx = fmaxf(fmaxf(fmaxf(v.x, v.y), fmaxf(v.z, v.w)), mx);
    }
    __shared__ float rm[256], rs[256];
    rm[tid] = mx; rs[tid] = sm;
    __syncthreads();
    for (int o = 128; o; o >>= 1) {
        if (tid < o) { rm[tid] = fmaxf(rm[tid], rm[tid+o]); rs[tid] += rs[tid+o]; }
        __syncthreads();
    }
    float M = fmaxf(rm[0] * TINV, 21.f), S = rs[0] * TINV;
    __syncthreads();
    float se = 0.f;
    for (int i = tid; i < Pp / 4; i += 256) {
        float4 v = pr[i];
        if (fmaxf(fmaxf(v.x, v.y), fmaxf(v.z, v.w)) * TINV > M - 30.f) {
            se += __expf(v.x*TINV - M) + __expf(v.y*TINV - M)
                + __expf(v.z*TINV - M) + __expf(v.w*TINV - M);
        }
    }
    rs[tid] = se;
    __syncthreads();
    for (int o = 128; o; o >>= 1) {
        if (tid < o) rs[tid] += rs[tid+o];
        __syncthreads();
    }
    if (tid == 0) { g_M[b] = M; g_szp[b] = S; g_sep[b] = rs[0]; }
}

// ---------------- K3: exact fp32 target logit ----------------
__global__ void k_target(const float* __restrict__ F, const int* __restrict__ tg) {
    int b = blockIdx.x, tid = threadIdx.x;
    const float4* f = (const float4*)(F + (size_t)tg[b] * Dd);
    const float4* x = (const float4*)(g_xn + (size_t)b * Dd);
    float d = 0.f;
    for (int i = tid; i < Dd / 4; i += 256) {
        float4 a = x[i], c = f[i];
        d += a.x*c.x + a.y*c.y + a.z*c.z + a.w*c.w;
    }
    #pragma unroll
    for (int o = 16; o; o >>= 1) d += __shfl_xor_sync(~0u, d, o);
    __shared__ float sh[8];
    if ((tid & 31) == 0) sh[tid >> 5] = d;
    __syncthreads();
    if (tid == 0) {
        float t = 0.f;
        #pragma unroll
        for (int i = 0; i < 8; i++) t += sh[i];
        g_zt[b] = t * TINV;
    }
}

// ---------------- K4: TMA + tf32 mma.sync GEMM, fused loss epilogue ----------
// Tile 256(M) x 128(N), K-chunk 32, 512 threads (16 warps 4x4), warp 64x32.
__global__ void __launch_bounds__(512, 1) k_gemm(
    const __grid_constant__ CUtensorMap tmA,
    const __grid_constant__ CUtensorMap tmB) {
    extern __shared__ char dsm[];
    __shared__ __align__(8) uint64_t s_bar[8];   // full[0..3], empty[0..3]

    int tid = threadIdx.x, lane = tid & 31, wid = tid >> 5;
    int wm = wid >> 2, wn = wid & 3;
    int n0 = blockIdx.x * BNg;
    uint32_t sb = (cvs(dsm) + 1023u) & ~1023u;
    uint32_t fullb = cvs(s_bar), emptyb = fullb + 32;

    if (tid == 0) {
        #pragma unroll
        for (int i = 0; i < NSTG; i++) {
            mbar_init(fullb + 8*i, 1);
            mbar_init(emptyb + 8*i, 512);
        }
    }
    __syncthreads();
    if (tid == 0) {
        #pragma unroll
        for (int p = 0; p < NSTG; p++) {
            mbar_expect(fullb + 8*p, STG_BY);
            tma2d(sb + p*STG_BY,        &tmA, p*KC, 0,  fullb + 8*p);
            tma2d(sb + p*STG_BY + A_BY, &tmB, p*KC, n0, fullb + 8*p);
        }
    }

    // per-thread fragment geometry (SW128 swizzle: addr = r*128 + ((c*4)^((r&7)<<4)))
    uint32_t X  = (uint32_t)(lane >> 2) << 4;   // (r&7)<<4 == (n&7)<<4 == lane>>2 <<4
    uint32_t q4 = (uint32_t)(lane & 3) << 2;
    uint32_t baseA[4], baseB[4];
    #pragma unroll
    for (int mt = 0; mt < 4; mt++)
        baseA[mt] = (uint32_t)(wm*64 + mt*16 + (lane >> 2)) * 128u;
    #pragma unroll
    for (int nt = 0; nt < 4; nt++)
        baseB[nt] = A_BY + (uint32_t)(wn*32 + nt*8 + (lane >> 2)) * 128u;

    float c[4][4][4];
    #pragma unroll
    for (int i = 0; i < 4; i++)
        #pragma unroll
        for (int j = 0; j < 4; j++)
            #pragma unroll
            for (int k = 0; k < 4; k++) c[i][j][k] = 0.f;

    for (int it = 0; it < NIT; it++) {
        int s = it & 3;
        uint32_t ph = (uint32_t)((it >> 2) & 1);
        mbar_wait(fullb + 8*s, ph);
        uint32_t sbase = sb + s * STG_BY;

        #pragma unroll
        for (int ks = 0; ks < 4; ks++) {
            uint32_t ko = (uint32_t)ks * 32u + q4;
            uint32_t o0 = ko ^ X, o1 = (ko + 16u) ^ X;
            uint32_t a[4][4], bb[4][2];
            #pragma unroll
            for (int mt = 0; mt < 4; mt++) {
                uint32_t p0 = sbase + baseA[mt];
                a[mt][0] = __float_as_uint(lds32(p0 + o0));
                a[mt][1] = __float_as_uint(lds32(p0 + 1024u + o0));
                a[mt][2] = __float_as_uint(lds32(p0 + o1));
                a[mt][3] = __float_as_uint(lds32(p0 + 1024u + o1));
            }
            #pragma unroll
            for (int nt = 0; nt < 4; nt++) {
                uint32_t p0 = sbase + baseB[nt];
                bb[nt][0] = __float_as_uint(lds32(p0 + o0));
                bb[nt][1] = __float_as_uint(lds32(p0 + o1));
            }
            #pragma unroll
            for (int mt = 0; mt < 4; mt++)
                #pragma unroll
                for (int nt = 0; nt < 4; nt++)
                    mma8(c[mt][nt], a[mt], bb[nt][0], bb[nt][1]);
        }

        mbar_arrive(emptyb + 8*s);
        if (tid == 0 && it + NSTG < NIT) {
            mbar_wait(emptyb + 8*s, ph);
            mbar_expect(fullb + 8*s, STG_BY);
            tma2d(sbase,        &tmA, (it + NSTG) * KC, 0,  fullb + 8*s);
            tma2d(sbase + A_BY, &tmB, (it + NSTG) * KC, n0, fullb + 8*s);
        }
    }
    __syncthreads();

    // fused epilogue: per-row sum + thresholded softmax numerator partials
    float* redv = (float*)dsm;          // [4 wn][256 rows]
    float* rede = redv + 1024;
    #pragma unroll
    for (int mt = 0; mt < 4; mt++) {
        int r0 = wm*64 + mt*16 + (lane >> 2);
        float M0 = g_M[r0], M1 = g_M[r0 + 8];
        float sv0 = 0.f, se0 = 0.f, sv1 = 0.f, se1 = 0.f;
        #pragma unroll
        for (int nt = 0; nt < 4; nt++) {
            float v;
            v = c[mt][nt][0]; sv0 += v; se0 += __expf(fmaf(TINV, v, -M0));
            v = c[mt][nt][1]; sv0 += v; se0 += __expf(fmaf(TINV, v, -M0));
            v = c[mt][nt][2]; sv1 += v; se1 += __expf(fmaf(TINV, v, -M1));
            v = c[mt][nt][3]; sv1 += v; se1 += __expf(fmaf(TINV, v, -M1));
        }
        #pragma unroll
        for (int o = 1; o <= 2; o <<= 1) {
            sv0 += __shfl_xor_sync(~0u, sv0, o);
            se0 += __shfl_xor_sync(~0u, se0, o);
            sv1 += __shfl_xor_sync(~0u, sv1, o);
            se1 += __shfl_xor_sync(~0u, se1, o);
        }
        if ((lane & 3) == 0) {
            redv[wn*256 + r0]     = sv0; rede[wn*256 + r0]     = se0;
            redv[wn*256 + r0 + 8] = sv1; rede[wn*256 + r0 + 8] = se1;
        }
    }
    __syncthreads();
    if (tid < 256) {
        float sv = redv[tid] + redv[256 + tid] + redv[512 + tid] + redv[768 + tid];
        float se = rede[tid] + rede[256 + tid] + rede[512 + tid] + rede[768 + tid];
        g_psv[(size_t)tid * NBLK + blockIdx.x] = sv;
        g_pse[(size_t)tid * NBLK + blockIdx.x] = se;
    }
}

// ---------------- K5: per-row combine over 512 CTA partials ----------------
__global__ void k_finalrow(void) {
    int b = blockIdx.x, tid = threadIdx.x;
    float sv = g_psv[(size_t)b * NBLK + tid] + g_psv[(size_t)b * NBLK + tid + 256];
    float se = g_pse[(size_t)b * NBLK + tid] + g_pse[(size_t)b * NBLK + tid + 256];
    __shared__ float rv[256], re[256];
    rv[tid] = sv; re[tid] = se;
    __syncthreads();
    for (int o = 128; o; o >>= 1) {
        if (tid < o) { rv[tid] += rv[tid+o]; re[tid] += re[tid+o]; }
        __syncthreads();
    }
    if (tid == 0) {
        float M = g_M[b];
        float lse = M + logf(g_sep[b] + re[0]);
        float T = g_szp[b] + TINV * rv[0];
        g_rowloss[b] = lse - (1.f - EPS_) * g_zt[b] - EPS_ * (T / (float)CTOT);
    }
}

// ---------------- K6: mean ----------------
__global__ void k_final(float* __restrict__ out) {
    int tid = threadIdx.x;
    float v = g_rowloss[tid];
    #pragma unroll
    for (int o = 16; o; o >>= 1) v += __shfl_xor_sync(~0u, v, o);
    __shared__ float sh[8];
    if ((tid & 31) == 0) sh[tid >> 5] = v;
    __syncthreads();
    if (tid == 0) {
        float s = 0.f;
        #pragma unroll
        for (int i = 0; i < 8; i++) s += sh[i];
        out[0] = s / (float)Bb;
    }
}

// ---------------------------------------------------------------------------
typedef CUresult (*PFN_tmapenc)(
    CUtensorMap*, CUtensorMapDataType, cuuint32_t, void*,
    const cuuint64_t*, const cuuint64_t*, const cuuint32_t*, const cuuint32_t*,
    CUtensorMapInterleave, CUtensorMapSwizzle, CUtensorMapL2promotion,
    CUtensorMapFloatOOBfill);

extern "C" void kernel_launch(void* const* d_in, const int* in_sizes, int n_in,
                              void* d_out, int out_size) {
    const float* inputs    = (const float*)d_in[0];
    const int*   targets   = (const int*)  d_in[1];
    const float* prototype = (const float*)d_in[2];
    const float* features  = (const float*)d_in[3];
    float* out = (float*)d_out;

    cudaFuncSetAttribute(k_gemm, cudaFuncAttributeMaxDynamicSharedMemorySize,
                         SMEM_DYN);

    PFN_tmapenc enc = nullptr;
    cudaDriverEntryPointQueryResult qr;
    cudaGetDriverEntryPointByVersion("cuTensorMapEncodeTiled", (void**)&enc,
                                     12000, cudaEnableDefault, &qr);

    void* xnp = nullptr;
    cudaGetSymbolAddress(&xnp, g_xn);

    CUtensorMap tmA, tmB;
    {
        cuuint64_t dims[2]    = {Dd, Bb};
        cuuint64_t strides[1] = {Dd * 4ull};
        cuuint32_t box[2]     = {KC, Bb};
        cuuint32_t es[2]      = {1, 1};
        enc(&tmA, CU_TENSOR_MAP_DATA_TYPE_FLOAT32, 2, xnp, dims, strides, box, es,
            CU_TENSOR_MAP_INTERLEAVE_NONE, CU_TENSOR_MAP_SWIZZLE_128B,
            CU_TENSOR_MAP_L2_PROMOTION_L2_128B, CU_TENSOR_MAP_FLOAT_OOB_FILL_NONE);
    }
    {
        cuuint64_t dims[2]    = {Dd, Nn};
        cuuint64_t strides[1] = {Dd * 4ull};
        cuuint32_t box[2]     = {KC, BNg};
        cuuint32_t es[2]      = {1, 1};
        enc(&tmB, CU_TENSOR_MAP_DATA_TYPE_FLOAT32, 2, (void*)features,
            dims, strides, box, es,
            CU_TENSOR_MAP_INTERLEAVE_NONE, CU_TENSOR_MAP_SWIZZLE_128B,
            CU_TENSOR_MAP_L2_PROMOTION_L2_128B, CU_TENSOR_MAP_FLOAT_OOB_FILL_NONE);
    }

    k_normalize<<<Bb, 256>>>(inputs);
    k_prep<<<Bb, 256>>>(prototype);
    k_target<<<Bb, 256>>>(features, targets);
    k_gemm<<<NBLK, 512, SMEM_DYN>>>(tmA, tmB);
    k_finalrow<<<Bb, 256>>>();
    k_final<<<1, 256>>>(out);
}

// round 7
// speedup vs baseline: 1.2649x; 1.2649x over previous
#include <cuda_runtime.h>
#include <cuda.h>
#include <cuda_bf16.h>
#include <math.h>
#include <stdint.h>

#define Bb 256
#define Dd 2048
#define Nn 65536
#define Pp 4096
#define CTOT (Pp + Nn)
#define TINV 20.0f
#define EPS_ 0.1f

#define BNg 128                  // N cols per CTA
#define NBLK (Nn / BNg)          // 512 CTAs
#define KC 32                    // K floats per stage (128 B rows)
#define NIT (Dd / KC)            // 64
#define NSTG 4
#define A_BY 32768               // 256 rows x 128 B
#define B_BY 16384               // 128 rows x 128 B
#define STG_BY (A_BY + B_BY)     // 49152
#define SMEM_DYN (NSTG * STG_BY + 1024)

__device__ __align__(128) float g_xn[Bb * Dd];
__device__ float g_M[Bb], g_szp[Bb], g_sep[Bb], g_zt[Bb], g_rowloss[Bb];
__device__ float g_psv[Bb * NBLK], g_pse[Bb * NBLK];

// ---------------- PTX helpers ----------------
__device__ __forceinline__ uint32_t cvs(const void* p) {
    return (uint32_t)__cvta_generic_to_shared(p);
}
__device__ __forceinline__ void mbar_init(uint32_t a, uint32_t c) {
    asm volatile("mbarrier.init.shared.b64 [%0], %1;" :: "r"(a), "r"(c) : "memory");
}
__device__ __forceinline__ void mbar_expect(uint32_t a, uint32_t tx) {
    asm volatile("mbarrier.arrive.expect_tx.shared.b64 _, [%0], %1;"
                 :: "r"(a), "r"(tx) : "memory");
}
__device__ __forceinline__ void mbar_arrive(uint32_t a) {
    asm volatile("mbarrier.arrive.shared.b64 _, [%0];" :: "r"(a) : "memory");
}
__device__ __forceinline__ void mbar_wait(uint32_t a, uint32_t ph) {
    asm volatile(
        "{\n\t.reg .pred P;\n\t"
        "W_%=:\n\t"
        "mbarrier.try_wait.parity.acquire.cta.shared::cta.b64 P, [%0], %1, 0x989680;\n\t"
        "@P bra D_%=;\n\t"
        "bra.uni W_%=;\n\t"
        "D_%=:\n\t}"
        :: "r"(a), "r"(ph) : "memory");
}
__device__ __forceinline__ void tma2d(uint32_t dst, const CUtensorMap* m,
                                      int x, int y, uint32_t bar) {
    asm volatile(
        "cp.async.bulk.tensor.2d.shared::cta.global.tile.mbarrier::complete_tx::bytes "
        "[%0], [%1, {%2, %3}], [%4];"
        :: "r"(dst), "l"(m), "r"(x), "r"(y), "r"(bar) : "memory");
}
__device__ __forceinline__ float lds32(uint32_t a) {
    float v;
    asm volatile("ld.shared.f32 %0, [%1];" : "=f"(v) : "r"(a));
    return v;
}
__device__ __forceinline__ void mma16(float c[4], const uint32_t a[4],
                                      uint32_t b0, uint32_t b1) {
    asm("mma.sync.aligned.m16n8k16.row.col.f32.bf16.bf16.f32 "
        "{%0,%1,%2,%3},{%4,%5,%6,%7},{%8,%9},{%0,%1,%2,%3};"
        : "+f"(c[0]), "+f"(c[1]), "+f"(c[2]), "+f"(c[3])
        : "r"(a[0]), "r"(a[1]), "r"(a[2]), "r"(a[3]), "r"(b0), "r"(b1));
}
// two parity-split loads -> ordered bf16x2 {lo=k_even, hi=k_odd}
__device__ __forceinline__ uint32_t pair_load(uint32_t base, uint32_t off,
                                              uint32_t e0, uint32_t e1,
                                              uint32_t X, bool geven) {
    float v0 = lds32(base + ((off + e0) ^ X));   // k = 2q + (g&1)
    float v1 = lds32(base + ((off + e1) ^ X));   // k = 2q + 1-(g&1)
    float lo = geven ? v0 : v1;
    float hi = geven ? v1 : v0;
    __nv_bfloat162 p = __floats2bfloat162_rn(lo, hi);
    return *(uint32_t*)&p;
}

// ---------------- K1: normalize inputs ----------------
__global__ void k_normalize(const float* __restrict__ in) {
    int row = blockIdx.x, tid = threadIdx.x;
    const float4* src = (const float4*)(in + (size_t)row * Dd);
    float4 v0 = src[tid], v1 = src[tid + 256];
    float ss = v0.x*v0.x + v0.y*v0.y + v0.z*v0.z + v0.w*v0.w
             + v1.x*v1.x + v1.y*v1.y + v1.z*v1.z + v1.w*v1.w;
    #pragma unroll
    for (int o = 16; o; o >>= 1) ss += __shfl_xor_sync(~0u, ss, o);
    __shared__ float sh[8];
    if ((tid & 31) == 0) sh[tid >> 5] = ss;
    __syncthreads();
    if (tid == 0) {
        float t = 0.f;
        #pragma unroll
        for (int i = 0; i < 8; i++) t += sh[i];
        sh[0] = rsqrtf(t);
    }
    __syncthreads();
    float iv = sh[0];
    float4* dst = (float4*)(g_xn + (size_t)row * Dd);
    v0.x*=iv; v0.y*=iv; v0.z*=iv; v0.w*=iv;
    v1.x*=iv; v1.y*=iv; v1.z*=iv; v1.w*=iv;
    dst[tid] = v0; dst[tid + 256] = v1;
}

// ---------------- K2: prototype stats ----------------
__global__ void k_prep(const float* __restrict__ proto) {
    int b = blockIdx.x, tid = threadIdx.x;
    const float4* pr = (const float4*)(proto + (size_t)b * Pp);
    float mx = -1e30f, sm = 0.f;
    #pragma unroll 4
    for (int i = tid; i < Pp / 4; i += 256) {
        float4 v = pr[i];
        sm += (v.x + v.y) + (v.z + v.w);
        mx = fmaxf(fmaxf(fmaxf(v.x, v.y), fmaxf(v.z, v.w)), mx);
    }
    __shared__ float rm[256], rs[256];
    rm[tid] = mx; rs[tid] = sm;
    __syncthreads();
    for (int o = 128; o; o >>= 1) {
        if (tid < o) { rm[tid] = fmaxf(rm[tid], rm[tid+o]); rs[tid] += rs[tid+o]; }
        __syncthreads();
    }
    float M = fmaxf(rm[0] * TINV, 21.f), S = rs[0] * TINV;
    __syncthreads();
    float se = 0.f;
    for (int i = tid; i < Pp / 4; i += 256) {
        float4 v = pr[i];
        if (fmaxf(fmaxf(v.x, v.y), fmaxf(v.z, v.w)) * TINV > M - 30.f) {
            se += __expf(v.x*TINV - M) + __expf(v.y*TINV - M)
                + __expf(v.z*TINV - M) + __expf(v.w*TINV - M);
        }
    }
    rs[tid] = se;
    __syncthreads();
    for (int o = 128; o; o >>= 1) {
        if (tid < o) rs[tid] += rs[tid+o];
        __syncthreads();
    }
    if (tid == 0) { g_M[b] = M; g_szp[b] = S; g_sep[b] = rs[0]; }
}

// ---------------- K3: exact fp32 target logit ----------------
__global__ void k_target(const float* __restrict__ F, const int* __restrict__ tg) {
    int b = blockIdx.x, tid = threadIdx.x;
    const float4* f = (const float4*)(F + (size_t)tg[b] * Dd);
    const float4* x = (const float4*)(g_xn + (size_t)b * Dd);
    float d = 0.f;
    for (int i = tid; i < Dd / 4; i += 256) {
        float4 a = x[i], c = f[i];
        d += a.x*c.x + a.y*c.y + a.z*c.z + a.w*c.w;
    }
    #pragma unroll
    for (int o = 16; o; o >>= 1) d += __shfl_xor_sync(~0u, d, o);
    __shared__ float sh[8];
    if ((tid & 31) == 0) sh[tid >> 5] = d;
    __syncthreads();
    if (tid == 0) {
        float t = 0.f;
        #pragma unroll
        for (int i = 0; i < 8; i++) t += sh[i];
        g_zt[b] = t * TINV;
    }
}

// ---------------- K4: TMA fp32 + bf16 mma.sync GEMM, fused epilogue ---------
// CTA tile 256(M) x 128(N); 256 threads, 8 warps as 4(m) x 2(n); warp 64x64.
__global__ void __launch_bounds__(256, 1) k_gemm(
    const __grid_constant__ CUtensorMap tmA,
    const __grid_constant__ CUtensorMap tmB) {
    extern __shared__ char dsm[];
    __shared__ __align__(8) uint64_t s_bar[8];   // full[0..3], empty[0..3]

    int tid = threadIdx.x, lane = tid & 31, wid = tid >> 5;
    int wm = wid >> 1, wn = wid & 1;
    int n0 = blockIdx.x * BNg;
    uint32_t sb = (cvs(dsm) + 1023u) & ~1023u;
    uint32_t fullb = cvs(s_bar), emptyb = fullb + 32;

    if (tid == 0) {
        #pragma unroll
        for (int i = 0; i < NSTG; i++) {
            mbar_init(fullb + 8*i, 1);
            mbar_init(emptyb + 8*i, 256);
        }
    }
    __syncthreads();
    if (tid == 0) {
        #pragma unroll
        for (int p = 0; p < NSTG; p++) {
            mbar_expect(fullb + 8*p, STG_BY);
            tma2d(sb + p*STG_BY,        &tmA, p*KC, 0,  fullb + 8*p);
            tma2d(sb + p*STG_BY + A_BY, &tmB, p*KC, n0, fullb + 8*p);
        }
    }

    // lane geometry
    int g = lane >> 2, q = lane & 3;
    bool geven = (g & 1) == 0;
    uint32_t X  = (uint32_t)g << 4;
    uint32_t e0 = ((uint32_t)q << 3) + ((uint32_t)(g & 1) << 2);
    uint32_t e1 = e0 ^ 4u;
    uint32_t rowA[4], rowB[2];
    #pragma unroll
    for (int mt = 0; mt < 4; mt++)
        rowA[mt] = (uint32_t)(wm*64 + mt*16 + g) * 128u;
    #pragma unroll
    for (int nh = 0; nh < 2; nh++)
        rowB[nh] = A_BY + (uint32_t)(wn*64 + nh*32 + g) * 128u;

    float c[4][8][4];
    #pragma unroll
    for (int i = 0; i < 4; i++)
        #pragma unroll
        for (int j = 0; j < 8; j++)
            #pragma unroll
            for (int k = 0; k < 4; k++) c[i][j][k] = 0.f;

    for (int it = 0; it < NIT; it++) {
        int s = it & 3;
        uint32_t ph = (uint32_t)((it >> 2) & 1);
        mbar_wait(fullb + 8*s, ph);
        uint32_t sbase = sb + s * STG_BY;

        #pragma unroll
        for (int kh = 0; kh < 2; kh++) {
            uint32_t khb = (uint32_t)kh * 64u;
            uint32_t a[4][4];
            #pragma unroll
            for (int mt = 0; mt < 4; mt++) {
                uint32_t p0 = sbase + rowA[mt];
                a[mt][0] = pair_load(p0,          khb,       e0, e1, X, geven);
                a[mt][1] = pair_load(p0 + 1024u,  khb,       e0, e1, X, geven);
                a[mt][2] = pair_load(p0,          khb + 32u, e0, e1, X, geven);
                a[mt][3] = pair_load(p0 + 1024u,  khb + 32u, e0, e1, X, geven);
            }
            #pragma unroll
            for (int nh = 0; nh < 2; nh++) {
                uint32_t bfr[4][2];
                #pragma unroll
                for (int ns = 0; ns < 4; ns++) {
                    uint32_t p0 = sbase + rowB[nh] + (uint32_t)ns * 1024u;
                    bfr[ns][0] = pair_load(p0, khb,       e0, e1, X, geven);
                    bfr[ns][1] = pair_load(p0, khb + 32u, e0, e1, X, geven);
                }
                #pragma unroll
                for (int mt = 0; mt < 4; mt++)
                    #pragma unroll
                    for (int ns = 0; ns < 4; ns++)
                        mma16(c[mt][nh*4 + ns], a[mt], bfr[ns][0], bfr[ns][1]);
            }
        }

        mbar_arrive(emptyb + 8*s);
        if (tid == 0 && it + NSTG < NIT) {
            mbar_wait(emptyb + 8*s, ph);
            mbar_expect(fullb + 8*s, STG_BY);
            tma2d(sbase,        &tmA, (it + NSTG) * KC, 0,  fullb + 8*s);
            tma2d(sbase + A_BY, &tmB, (it + NSTG) * KC, n0, fullb + 8*s);
        }
    }
    __syncthreads();

    // fused epilogue: per-row sum + softmax numerator partials
    float* redv = (float*)dsm;          // [2 wn][256 rows]
    float* rede = redv + 512;
    #pragma unroll
    for (int mt = 0; mt < 4; mt++) {
        int r0 = wm*64 + mt*16 + g;
        float M0 = g_M[r0], M1 = g_M[r0 + 8];
        float sv0 = 0.f, se0 = 0.f, sv1 = 0.f, se1 = 0.f;
        #pragma unroll
        for (int nt = 0; nt < 8; nt++) {
            float v;
            v = c[mt][nt][0]; sv0 += v; se0 += __expf(fmaf(TINV, v, -M0));
            v = c[mt][nt][1]; sv0 += v; se0 += __expf(fmaf(TINV, v, -M0));
            v = c[mt][nt][2]; sv1 += v; se1 += __expf(fmaf(TINV, v, -M1));
            v = c[mt][nt][3]; sv1 += v; se1 += __expf(fmaf(TINV, v, -M1));
        }
        #pragma unroll
        for (int o = 1; o <= 2; o <<= 1) {
            sv0 += __shfl_xor_sync(~0u, sv0, o);
            se0 += __shfl_xor_sync(~0u, se0, o);
            sv1 += __shfl_xor_sync(~0u, sv1, o);
            se1 += __shfl_xor_sync(~0u, se1, o);
        }
        if (q == 0) {
            redv[wn*256 + r0]     = sv0; rede[wn*256 + r0]     = se0;
            redv[wn*256 + r0 + 8] = sv1; rede[wn*256 + r0 + 8] = se1;
        }
    }
    __syncthreads();
    {
        float sv = redv[tid] + redv[256 + tid];
        float se = rede[tid] + rede[256 + tid];
        g_psv[(size_t)tid * NBLK + blockIdx.x] = sv;
        g_pse[(size_t)tid * NBLK + blockIdx.x] = se;
    }
}

// ---------------- K5: per-row combine over 512 CTA partials ----------------
__global__ void k_finalrow(void) {
    int b = blockIdx.x, tid = threadIdx.x;
    float sv = g_psv[(size_t)b * NBLK + tid] + g_psv[(size_t)b * NBLK + tid + 256];
    float se = g_pse[(size_t)b * NBLK + tid] + g_pse[(size_t)b * NBLK + tid + 256];
    __shared__ float rv[256], re[256];
    rv[tid] = sv; re[tid] = se;
    __syncthreads();
    for (int o = 128; o; o >>= 1) {
        if (tid < o) { rv[tid] += rv[tid+o]; re[tid] += re[tid+o]; }
        __syncthreads();
    }
    if (tid == 0) {
        float M = g_M[b];
        float lse = M + logf(g_sep[b] + re[0]);
        float T = g_szp[b] + TINV * rv[0];
        g_rowloss[b] = lse - (1.f - EPS_) * g_zt[b] - EPS_ * (T / (float)CTOT);
    }
}

// ---------------- K6: mean ----------------
__global__ void k_final(float* __restrict__ out) {
    int tid = threadIdx.x;
    float v = g_rowloss[tid];
    #pragma unroll
    for (int o = 16; o; o >>= 1) v += __shfl_xor_sync(~0u, v, o);
    __shared__ float sh[8];
    if ((tid & 31) == 0) sh[tid >> 5] = v;
    __syncthreads();
    if (tid == 0) {
        float s = 0.f;
        #pragma unroll
        for (int i = 0; i < 8; i++) s += sh[i];
        out[0] = s / (float)Bb;
    }
}

// ---------------------------------------------------------------------------
typedef CUresult (*PFN_tmapenc)(
    CUtensorMap*, CUtensorMapDataType, cuuint32_t, void*,
    const cuuint64_t*, const cuuint64_t*, const cuuint32_t*, const cuuint32_t*,
    CUtensorMapInterleave, CUtensorMapSwizzle, CUtensorMapL2promotion,
    CUtensorMapFloatOOBfill);

extern "C" void kernel_launch(void* const* d_in, const int* in_sizes, int n_in,
                              void* d_out, int out_size) {
    const float* inputs    = (const float*)d_in[0];
    const int*   targets   = (const int*)  d_in[1];
    const float* prototype = (const float*)d_in[2];
    const float* features  = (const float*)d_in[3];
    float* out = (float*)d_out;

    cudaFuncSetAttribute(k_gemm, cudaFuncAttributeMaxDynamicSharedMemorySize,
                         SMEM_DYN);

    PFN_tmapenc enc = nullptr;
    cudaDriverEntryPointQueryResult qr;
    cudaGetDriverEntryPointByVersion("cuTensorMapEncodeTiled", (void**)&enc,
                                     12000, cudaEnableDefault, &qr);

    void* xnp = nullptr;
    cudaGetSymbolAddress(&xnp, g_xn);

    CUtensorMap tmA, tmB;
    {
        cuuint64_t dims[2]    = {Dd, Bb};
        cuuint64_t strides[1] = {Dd * 4ull};
        cuuint32_t box[2]     = {KC, Bb};
        cuuint32_t es[2]      = {1, 1};
        enc(&tmA, CU_TENSOR_MAP_DATA_TYPE_FLOAT32, 2, xnp, dims, strides, box, es,
            CU_TENSOR_MAP_INTERLEAVE_NONE, CU_TENSOR_MAP_SWIZZLE_128B,
            CU_TENSOR_MAP_L2_PROMOTION_L2_128B, CU_TENSOR_MAP_FLOAT_OOB_FILL_NONE);
    }
    {
        cuuint64_t dims[2]    = {Dd, Nn};
        cuuint64_t strides[1] = {Dd * 4ull};
        cuuint32_t box[2]     = {KC, BNg};
        cuuint32_t es[2]      = {1, 1};
        enc(&tmB, CU_TENSOR_MAP_DATA_TYPE_FLOAT32, 2, (void*)features,
            dims, strides, box, es,
            CU_TENSOR_MAP_INTERLEAVE_NONE, CU_TENSOR_MAP_SWIZZLE_128B,
            CU_TENSOR_MAP_L2_PROMOTION_L2_128B, CU_TENSOR_MAP_FLOAT_OOB_FILL_NONE);
    }

    k_normalize<<<Bb, 256>>>(inputs);
    k_prep<<<Bb, 256>>>(prototype);
    k_target<<<Bb, 256>>>(features, targets);
    k_gemm<<<NBLK, 256, SMEM_DYN>>>(tmA, tmB);
    k_finalrow<<<Bb, 256>>>();
    k_final<<<1, 256>>>(out);
}

// round 8
// speedup vs baseline: 1.4659x; 1.1589x over previous
#include <cuda_runtime.h>
#include <cuda.h>
#include <cuda_bf16.h>
#include <math.h>
#include <stdint.h>

#define Bb 256
#define Dd 2048
#define Nn 65536
#define Pp 4096
#define CTOT (Pp + Nn)
#define TINV 20.0f
#define EPS_ 0.1f

#define BNg 128                  // N cols per CTA
#define NBLK (Nn / BNg)          // 512 CTAs
#define KC 64                    // K floats per stage
#define NIT (Dd / KC)            // 32 stages
#define NSTG 2
#define A_BY 32768               // A bf16: 256 rows x 128 B
#define BF_BY 32768              // B fp32: 2 chunks x (128 rows x 128 B)
#define BB_BY 16384              // B bf16: 128 rows x 128 B
#define STG_BY (A_BY + BF_BY + BB_BY)   // 81920
#define SMEM_DYN (NSTG * STG_BY + 1024)

__device__ __align__(128) float g_xn[Bb * Dd];
__device__ __align__(128) __nv_bfloat16 g_xnb[Bb * Dd];
__device__ float g_M[Bb], g_szp[Bb], g_sep[Bb], g_zt[Bb], g_rowloss[Bb];
__device__ float g_psv[Bb * NBLK], g_pse[Bb * NBLK];

// ---------------- PTX helpers ----------------
__device__ __forceinline__ uint32_t cvs(const void* p) {
    return (uint32_t)__cvta_generic_to_shared(p);
}
__device__ __forceinline__ void mbar_init(uint32_t a, uint32_t c) {
    asm volatile("mbarrier.init.shared.b64 [%0], %1;" :: "r"(a), "r"(c) : "memory");
}
__device__ __forceinline__ void mbar_expect(uint32_t a, uint32_t tx) {
    asm volatile("mbarrier.arrive.expect_tx.shared.b64 _, [%0], %1;"
                 :: "r"(a), "r"(tx) : "memory");
}
__device__ __forceinline__ void mbar_arrive(uint32_t a) {
    asm volatile("mbarrier.arrive.shared.b64 _, [%0];" :: "r"(a) : "memory");
}
__device__ __forceinline__ void mbar_wait(uint32_t a, uint32_t ph) {
    asm volatile(
        "{\n\t.reg .pred P;\n\t"
        "W_%=:\n\t"
        "mbarrier.try_wait.parity.acquire.cta.shared::cta.b64 P, [%0], %1, 0x989680;\n\t"
        "@P bra D_%=;\n\t"
        "bra.uni W_%=;\n\t"
        "D_%=:\n\t}"
        :: "r"(a), "r"(ph) : "memory");
}
__device__ __forceinline__ void tma2d(uint32_t dst, const CUtensorMap* m,
                                      int x, int y, uint32_t bar) {
    asm volatile(
        "cp.async.bulk.tensor.2d.shared::cta.global.tile.mbarrier::complete_tx::bytes "
        "[%0], [%1, {%2, %3}], [%4];"
        :: "r"(dst), "l"(m), "r"(x), "r"(y), "r"(bar) : "memory");
}
__device__ __forceinline__ void ldsm4(uint32_t& r0, uint32_t& r1, uint32_t& r2,
                                      uint32_t& r3, uint32_t addr) {
    asm volatile(
        "ldmatrix.sync.aligned.m8n8.x4.shared.b16 {%0,%1,%2,%3}, [%4];"
        : "=r"(r0), "=r"(r1), "=r"(r2), "=r"(r3) : "r"(addr));
}
__device__ __forceinline__ void mma16(float c[4], const uint32_t a[4],
                                      uint32_t b0, uint32_t b1) {
    asm("mma.sync.aligned.m16n8k16.row.col.f32.bf16.bf16.f32 "
        "{%0,%1,%2,%3},{%4,%5,%6,%7},{%8,%9},{%0,%1,%2,%3};"
        : "+f"(c[0]), "+f"(c[1]), "+f"(c[2]), "+f"(c[3])
        : "r"(a[0]), "r"(a[1]), "r"(a[2]), "r"(a[3]), "r"(b0), "r"(b1));
}
__device__ __forceinline__ uint32_t pack2(float a, float b) {
    __nv_bfloat162 p = __floats2bfloat162_rn(a, b);
    return *(uint32_t*)&p;
}

// ---------------- K1: normalize inputs (fp32 + bf16 out) ----------------
__global__ void k_normalize(const float* __restrict__ in) {
    int row = blockIdx.x, tid = threadIdx.x;
    const float4* src = (const float4*)(in + (size_t)row * Dd);
    float4 v0 = src[tid], v1 = src[tid + 256];
    float ss = v0.x*v0.x + v0.y*v0.y + v0.z*v0.z + v0.w*v0.w
             + v1.x*v1.x + v1.y*v1.y + v1.z*v1.z + v1.w*v1.w;
    #pragma unroll
    for (int o = 16; o; o >>= 1) ss += __shfl_xor_sync(~0u, ss, o);
    __shared__ float sh[8];
    if ((tid & 31) == 0) sh[tid >> 5] = ss;
    __syncthreads();
    if (tid == 0) {
        float t = 0.f;
        #pragma unroll
        for (int i = 0; i < 8; i++) t += sh[i];
        sh[0] = rsqrtf(t);
    }
    __syncthreads();
    float iv = sh[0];
    v0.x*=iv; v0.y*=iv; v0.z*=iv; v0.w*=iv;
    v1.x*=iv; v1.y*=iv; v1.z*=iv; v1.w*=iv;
    float4* dst = (float4*)(g_xn + (size_t)row * Dd);
    dst[tid] = v0; dst[tid + 256] = v1;
    uint2* bdst = (uint2*)(g_xnb + (size_t)row * Dd);
    bdst[tid]       = make_uint2(pack2(v0.x, v0.y), pack2(v0.z, v0.w));
    bdst[tid + 256] = make_uint2(pack2(v1.x, v1.y), pack2(v1.z, v1.w));
}

// ---------------- K2: prototype stats ----------------
__global__ void k_prep(const float* __restrict__ proto) {
    int b = blockIdx.x, tid = threadIdx.x;
    const float4* pr = (const float4*)(proto + (size_t)b * Pp);
    float mx = -1e30f, sm = 0.f;
    #pragma unroll 4
    for (int i = tid; i < Pp / 4; i += 256) {
        float4 v = pr[i];
        sm += (v.x + v.y) + (v.z + v.w);
        mx = fmaxf(fmaxf(fmaxf(v.x, v.y), fmaxf(v.z, v.w)), mx);
    }
    __shared__ float rm[256], rs[256];
    rm[tid] = mx; rs[tid] = sm;
    __syncthreads();
    for (int o = 128; o; o >>= 1) {
        if (tid < o) { rm[tid] = fmaxf(rm[tid], rm[tid+o]); rs[tid] += rs[tid+o]; }
        __syncthreads();
    }
    float M = fmaxf(rm[0] * TINV, 21.f), S = rs[0] * TINV;
    __syncthreads();
    float se = 0.f;
    for (int i = tid; i < Pp / 4; i += 256) {
        float4 v = pr[i];
        if (fmaxf(fmaxf(v.x, v.y), fmaxf(v.z, v.w)) * TINV > M - 30.f) {
            se += __expf(v.x*TINV - M) + __expf(v.y*TINV - M)
                + __expf(v.z*TINV - M) + __expf(v.w*TINV - M);
        }
    }
    rs[tid] = se;
    __syncthreads();
    for (int o = 128; o; o >>= 1) {
        if (tid < o) rs[tid] += rs[tid+o];
        __syncthreads();
    }
    if (tid == 0) { g_M[b] = M; g_szp[b] = S; g_sep[b] = rs[0]; }
}

// ---------------- K3: exact fp32 target logit ----------------
__global__ void k_target(const float* __restrict__ F, const int* __restrict__ tg) {
    int b = blockIdx.x, tid = threadIdx.x;
    const float4* f = (const float4*)(F + (size_t)tg[b] * Dd);
    const float4* x = (const float4*)(g_xn + (size_t)b * Dd);
    float d = 0.f;
    for (int i = tid; i < Dd / 4; i += 256) {
        float4 a = x[i], c = f[i];
        d += a.x*c.x + a.y*c.y + a.z*c.z + a.w*c.w;
    }
    #pragma unroll
    for (int o = 16; o; o >>= 1) d += __shfl_xor_sync(~0u, d, o);
    __shared__ float sh[8];
    if ((tid & 31) == 0) sh[tid >> 5] = d;
    __syncthreads();
    if (tid == 0) {
        float t = 0.f;
        #pragma unroll
        for (int i = 0; i < 8; i++) t += sh[i];
        g_zt[b] = t * TINV;
    }
}

// ---------------- K4: TMA + ldmatrix bf16 GEMM, fused epilogue ----------
// CTA tile 256(M) x 128(N), stage k=64; 256 threads, 8 warps 4(m) x 2(n).
// A arrives bf16 via TMA. B arrives fp32; converted to a bf16 smem tile
// once per stage, then consumed by ldmatrix.
__global__ void __launch_bounds__(256, 1) k_gemm(
    const __grid_constant__ CUtensorMap tmA,
    const __grid_constant__ CUtensorMap tmB) {
    extern __shared__ char dsm[];
    __shared__ __align__(8) uint64_t s_bar[4];   // full[0..1], empty[0..1]

    int tid = threadIdx.x, lane = tid & 31, wid = tid >> 5;
    int wm = wid >> 1, wn = wid & 1;
    int n0 = blockIdx.x * BNg;
    uint32_t sb = (cvs(dsm) + 1023u) & ~1023u;
    uint32_t fullb = cvs(s_bar), emptyb = fullb + 16;

    if (tid == 0) {
        #pragma unroll
        for (int i = 0; i < NSTG; i++) {
            mbar_init(fullb + 8*i, 1);
            mbar_init(emptyb + 8*i, 256);
        }
    }
    __syncthreads();
    if (tid == 0) {
        #pragma unroll
        for (int p = 0; p < NSTG; p++) {
            mbar_expect(fullb + 8*p, A_BY + BF_BY);
            tma2d(sb + p*STG_BY,                  &tmA, p*KC,      0,  fullb + 8*p);
            tma2d(sb + p*STG_BY + A_BY,           &tmB, p*KC,      n0, fullb + 8*p);
            tma2d(sb + p*STG_BY + A_BY + 16384,   &tmB, p*KC + 32, n0, fullb + 8*p);
        }
    }

    // ---- conversion geometry: thread -> (n row, k chunk) ----
    int cn = tid >> 1, cc = tid & 1;
    uint32_t Xc = (uint32_t)(cn & 7) << 4;
    uint32_t csrc = (uint32_t)(A_BY + cc * 16384 + cn * 128);
    uint32_t cdst = (uint32_t)(A_BY + BF_BY + cn * 128);
    uint32_t cdo  = (uint32_t)cc * 64u;

    // ---- ldmatrix lane geometry ----
    int l15 = lane & 15;
    uint32_t aHi = (uint32_t)(lane >> 4) << 4;         // 0 / 16
    uint32_t rowAddrA[4], Xa[4];
    #pragma unroll
    for (int mt = 0; mt < 4; mt++) {
        int row = wm*64 + mt*16 + l15;
        rowAddrA[mt] = (uint32_t)row * 128u;
        Xa[mt] = (uint32_t)(row & 7) << 4;
    }
    int j = lane >> 3;
    uint32_t bCol = (uint32_t)(j & 1) << 4;            // 0 / 16
    uint32_t rowAddrB[4], Xb[4];
    #pragma unroll
    for (int u = 0; u < 4; u++) {
        int row = wn*64 + u*16 + (lane & 7) + (j >> 1) * 8;
        rowAddrB[u] = (uint32_t)(A_BY + BF_BY) + (uint32_t)row * 128u;
        Xb[u] = (uint32_t)(row & 7) << 4;
    }

    float c[4][8][4];
    #pragma unroll
    for (int i = 0; i < 4; i++)
        #pragma unroll
        for (int jj = 0; jj < 8; jj++)
            #pragma unroll
            for (int k = 0; k < 4; k++) c[i][jj][k] = 0.f;

    for (int it = 0; it < NIT; it++) {
        int s = it & 1;
        uint32_t ph = (uint32_t)((it >> 1) & 1);
        mbar_wait(fullb + 8*s, ph);
        uint32_t sbase = sb + s * STG_BY;

        // ---- convert B fp32 -> bf16 (this thread's 32 floats) ----
        {
            uint32_t srcb = sbase + csrc;
            uint32_t dstb = sbase + cdst;
            #pragma unroll
            for (int j2 = 0; j2 < 4; j2++) {
                float4 lo, hi;
                asm volatile("ld.shared.v4.f32 {%0,%1,%2,%3}, [%4];"
                    : "=f"(lo.x), "=f"(lo.y), "=f"(lo.z), "=f"(lo.w)
                    : "r"(srcb + (((uint32_t)(2*j2) * 16u) ^ Xc)));
                asm volatile("ld.shared.v4.f32 {%0,%1,%2,%3}, [%4];"
                    : "=f"(hi.x), "=f"(hi.y), "=f"(hi.z), "=f"(hi.w)
                    : "r"(srcb + (((uint32_t)(2*j2+1) * 16u) ^ Xc)));
                uint32_t p0 = pack2(lo.x, lo.y), p1 = pack2(lo.z, lo.w);
                uint32_t p2 = pack2(hi.x, hi.y), p3 = pack2(hi.z, hi.w);
                asm volatile("st.shared.v4.b32 [%0], {%1,%2,%3,%4};"
                    :: "r"(dstb + ((cdo + (uint32_t)j2 * 16u) ^ Xc)),
                       "r"(p0), "r"(p1), "r"(p2), "r"(p3) : "memory");
            }
        }
        __syncthreads();   // bf16 B tile visible to all warps

        // ---- compute: 4 k16-steps ----
        #pragma unroll
        for (int s4 = 0; s4 < 4; s4++) {
            uint32_t kb = (uint32_t)s4 * 32u;
            uint32_t a[4][4], bfr[4][4];
            #pragma unroll
            for (int mt = 0; mt < 4; mt++)
                ldsm4(a[mt][0], a[mt][1], a[mt][2], a[mt][3],
                      sbase + rowAddrA[mt] + ((kb + aHi) ^ Xa[mt]));
            #pragma unroll
            for (int u = 0; u < 4; u++)
                ldsm4(bfr[u][0], bfr[u][1], bfr[u][2], bfr[u][3],
                      sbase + rowAddrB[u] + ((kb + bCol) ^ Xb[u]));
            #pragma unroll
            for (int mt = 0; mt < 4; mt++)
                #pragma unroll
                for (int u = 0; u < 4; u++) {
                    mma16(c[mt][2*u],     a[mt], bfr[u][0], bfr[u][1]);
                    mma16(c[mt][2*u + 1], a[mt], bfr[u][2], bfr[u][3]);
                }
        }

        __syncthreads();   // all reads of stage s done before reuse
        mbar_arrive(emptyb + 8*s);
        if (tid == 0 && it + NSTG < NIT) {
            mbar_wait(emptyb + 8*s, ph);
            mbar_expect(fullb + 8*s, A_BY + BF_BY);
            int k0 = (it + NSTG) * KC;
            tma2d(sbase,                &tmA, k0,      0,  fullb + 8*s);
            tma2d(sbase + A_BY,         &tmB, k0,      n0, fullb + 8*s);
            tma2d(sbase + A_BY + 16384, &tmB, k0 + 32, n0, fullb + 8*s);
        }
    }
    __syncthreads();

    // ---- fused epilogue: per-row sum + softmax numerator partials ----
    int g = lane >> 2, q = lane & 3;
    float* redv = (float*)dsm;          // [2 wn][256 rows]
    float* rede = redv + 512;
    #pragma unroll
    for (int mt = 0; mt < 4; mt++) {
        int r0 = wm*64 + mt*16 + g;
        float M0 = g_M[r0], M1 = g_M[r0 + 8];
        float sv0 = 0.f, se0 = 0.f, sv1 = 0.f, se1 = 0.f;
        #pragma unroll
        for (int nt = 0; nt < 8; nt++) {
            float v;
            v = c[mt][nt][0]; sv0 += v; se0 += __expf(fmaf(TINV, v, -M0));
            v = c[mt][nt][1]; sv0 += v; se0 += __expf(fmaf(TINV, v, -M0));
            v = c[mt][nt][2]; sv1 += v; se1 += __expf(fmaf(TINV, v, -M1));
            v = c[mt][nt][3]; sv1 += v; se1 += __expf(fmaf(TINV, v, -M1));
        }
        #pragma unroll
        for (int o = 1; o <= 2; o <<= 1) {
            sv0 += __shfl_xor_sync(~0u, sv0, o);
            se0 += __shfl_xor_sync(~0u, se0, o);
            sv1 += __shfl_xor_sync(~0u, sv1, o);
            se1 += __shfl_xor_sync(~0u, se1, o);
        }
        if (q == 0) {
            redv[wn*256 + r0]     = sv0; rede[wn*256 + r0]     = se0;
            redv[wn*256 + r0 + 8] = sv1; rede[wn*256 + r0 + 8] = se1;
        }
    }
    __syncthreads();
    {
        float sv = redv[tid] + redv[256 + tid];
        float se = rede[tid] + rede[256 + tid];
        g_psv[(size_t)tid * NBLK + blockIdx.x] = sv;
        g_pse[(size_t)tid * NBLK + blockIdx.x] = se;
    }
}

// ---------------- K5: per-row combine over 512 CTA partials ----------------
__global__ void k_finalrow(void) {
    int b = blockIdx.x, tid = threadIdx.x;
    float sv = g_psv[(size_t)b * NBLK + tid] + g_psv[(size_t)b * NBLK + tid + 256];
    float se = g_pse[(size_t)b * NBLK + tid] + g_pse[(size_t)b * NBLK + tid + 256];
    __shared__ float rv[256], re[256];
    rv[tid] = sv; re[tid] = se;
    __syncthreads();
    for (int o = 128; o; o >>= 1) {
        if (tid < o) { rv[tid] += rv[tid+o]; re[tid] += re[tid+o]; }
        __syncthreads();
    }
    if (tid == 0) {
        float M = g_M[b];
        float lse = M + logf(g_sep[b] + re[0]);
        float T = g_szp[b] + TINV * rv[0];
        g_rowloss[b] = lse - (1.f - EPS_) * g_zt[b] - EPS_ * (T / (float)CTOT);
    }
}

// ---------------- K6: mean ----------------
__global__ void k_final(float* __restrict__ out) {
    int tid = threadIdx.x;
    float v = g_rowloss[tid];
    #pragma unroll
    for (int o = 16; o; o >>= 1) v += __shfl_xor_sync(~0u, v, o);
    __shared__ float sh[8];
    if ((tid & 31) == 0) sh[tid >> 5] = v;
    __syncthreads();
    if (tid == 0) {
        float s = 0.f;
        #pragma unroll
        for (int i = 0; i < 8; i++) s += sh[i];
        out[0] = s / (float)Bb;
    }
}

// ---------------------------------------------------------------------------
typedef CUresult (*PFN_tmapenc)(
    CUtensorMap*, CUtensorMapDataType, cuuint32_t, void*,
    const cuuint64_t*, const cuuint64_t*, const cuuint32_t*, const cuuint32_t*,
    CUtensorMapInterleave, CUtensorMapSwizzle, CUtensorMapL2promotion,
    CUtensorMapFloatOOBfill);

extern "C" void kernel_launch(void* const* d_in, const int* in_sizes, int n_in,
                              void* d_out, int out_size) {
    const float* inputs    = (const float*)d_in[0];
    const int*   targets   = (const int*)  d_in[1];
    const float* prototype = (const float*)d_in[2];
    const float* features  = (const float*)d_in[3];
    float* out = (float*)d_out;

    cudaFuncSetAttribute(k_gemm, cudaFuncAttributeMaxDynamicSharedMemorySize,
                         SMEM_DYN);

    PFN_tmapenc enc = nullptr;
    cudaDriverEntryPointQueryResult qr;
    cudaGetDriverEntryPointByVersion("cuTensorMapEncodeTiled", (void**)&enc,
                                     12000, cudaEnableDefault, &qr);

    void* xnbp = nullptr;
    cudaGetSymbolAddress(&xnbp, g_xnb);

    CUtensorMap tmA, tmB;
    {
        cuuint64_t dims[2]    = {Dd, Bb};
        cuuint64_t strides[1] = {Dd * 2ull};
        cuuint32_t box[2]     = {KC, Bb};          // 64 bf16 = 128 B x 256 rows
        cuuint32_t es[2]      = {1, 1};
        enc(&tmA, CU_TENSOR_MAP_DATA_TYPE_BFLOAT16, 2, xnbp, dims, strides, box, es,
            CU_TENSOR_MAP_INTERLEAVE_NONE, CU_TENSOR_MAP_SWIZZLE_128B,
            CU_TENSOR_MAP_L2_PROMOTION_L2_128B, CU_TENSOR_MAP_FLOAT_OOB_FILL_NONE);
    }
    {
        cuuint64_t dims[2]    = {Dd, Nn};
        cuuint64_t strides[1] = {Dd * 4ull};
        cuuint32_t box[2]     = {32, BNg};         // 32 f32 = 128 B x 128 rows
        cuuint32_t es[2]      = {1, 1};
        enc(&tmB, CU_TENSOR_MAP_DATA_TYPE_FLOAT32, 2, (void*)features,
            dims, strides, box, es,
            CU_TENSOR_MAP_INTERLEAVE_NONE, CU_TENSOR_MAP_SWIZZLE_128B,
            CU_TENSOR_MAP_L2_PROMOTION_L2_128B, CU_TENSOR_MAP_FLOAT_OOB_FILL_NONE);
    }

    k_normalize<<<Bb, 256>>>(inputs);
    k_prep<<<Bb, 256>>>(prototype);
    k_target<<<Bb, 256>>>(features, targets);
    k_gemm<<<NBLK, 256, SMEM_DYN>>>(tmA, tmB);
    k_finalrow<<<Bb, 256>>>();
    k_final<<<1, 256>>>(out);
}

// round 9
// speedup vs baseline: 1.5989x; 1.0907x over previous
#include <cuda_runtime.h>
#include <cuda.h>
#include <cuda_bf16.h>
#include <math.h>
#include <stdint.h>

#define Bb 256
#define Dd 2048
#define Nn 65536
#define Pp 4096
#define CTOT (Pp + Nn)
#define TINV 20.0f
#define EPS_ 0.1f

#define BNg 128                  // N cols per CTA
#define NBLK (Nn / BNg)          // 512 CTAs
#define KC 64                    // K floats per stage
#define NIT (Dd / KC)            // 32 stages
#define NSTG 2
#define A_BY 32768               // A bf16: 256 rows x 128 B
#define BF_BY 32768              // B fp32: 2 chunks x (128 rows x 128 B)
#define BB_BY 16384              // B bf16: 128 rows x 128 B
#define STG_BY (A_BY + BF_BY + BB_BY)   // 81920
#define SMEM_DYN (NSTG * STG_BY + 1024)

__device__ __align__(128) float g_xn[Bb * Dd];
__device__ __align__(128) __nv_bfloat16 g_xnb[Bb * Dd];
__device__ float g_M[Bb], g_szp[Bb], g_sep[Bb], g_zt[Bb], g_rowloss[Bb];
__device__ float g_psv[Bb * NBLK], g_pse[Bb * NBLK];

// ---------------- PTX helpers ----------------
__device__ __forceinline__ uint32_t cvs(const void* p) {
    return (uint32_t)__cvta_generic_to_shared(p);
}
__device__ __forceinline__ void mbar_init(uint32_t a, uint32_t c) {
    asm volatile("mbarrier.init.shared.b64 [%0], %1;" :: "r"(a), "r"(c) : "memory");
}
__device__ __forceinline__ void mbar_expect(uint32_t a, uint32_t tx) {
    asm volatile("mbarrier.arrive.expect_tx.shared.b64 _, [%0], %1;"
                 :: "r"(a), "r"(tx) : "memory");
}
__device__ __forceinline__ void mbar_wait(uint32_t a, uint32_t ph) {
    asm volatile(
        "{\n\t.reg .pred P;\n\t"
        "W_%=:\n\t"
        "mbarrier.try_wait.parity.acquire.cta.shared::cta.b64 P, [%0], %1, 0x989680;\n\t"
        "@P bra D_%=;\n\t"
        "bra.uni W_%=;\n\t"
        "D_%=:\n\t}"
        :: "r"(a), "r"(ph) : "memory");
}
__device__ __forceinline__ void tma2d(uint32_t dst, const CUtensorMap* m,
                                      int x, int y, uint32_t bar) {
    asm volatile(
        "cp.async.bulk.tensor.2d.shared::cta.global.tile.mbarrier::complete_tx::bytes "
        "[%0], [%1, {%2, %3}], [%4];"
        :: "r"(dst), "l"(m), "r"(x), "r"(y), "r"(bar) : "memory");
}
__device__ __forceinline__ void ldsm4(uint32_t& r0, uint32_t& r1, uint32_t& r2,
                                      uint32_t& r3, uint32_t addr) {
    asm volatile(
        "ldmatrix.sync.aligned.m8n8.x4.shared.b16 {%0,%1,%2,%3}, [%4];"
        : "=r"(r0), "=r"(r1), "=r"(r2), "=r"(r3) : "r"(addr));
}
__device__ __forceinline__ void mma16(float c[4], const uint32_t a[4],
                                      uint32_t b0, uint32_t b1) {
    asm("mma.sync.aligned.m16n8k16.row.col.f32.bf16.bf16.f32 "
        "{%0,%1,%2,%3},{%4,%5,%6,%7},{%8,%9},{%0,%1,%2,%3};"
        : "+f"(c[0]), "+f"(c[1]), "+f"(c[2]), "+f"(c[3])
        : "r"(a[0]), "r"(a[1]), "r"(a[2]), "r"(a[3]), "r"(b0), "r"(b1));
}
__device__ __forceinline__ uint32_t pack2(float a, float b) {
    __nv_bfloat162 p = __floats2bfloat162_rn(a, b);
    return *(uint32_t*)&p;
}

// ---------------- K1: normalize inputs (fp32 + bf16 out) ----------------
__global__ void k_normalize(const float* __restrict__ in) {
    int row = blockIdx.x, tid = threadIdx.x;
    const float4* src = (const float4*)(in + (size_t)row * Dd);
    float4 v0 = src[tid], v1 = src[tid + 256];
    float ss = v0.x*v0.x + v0.y*v0.y + v0.z*v0.z + v0.w*v0.w
             + v1.x*v1.x + v1.y*v1.y + v1.z*v1.z + v1.w*v1.w;
    #pragma unroll
    for (int o = 16; o; o >>= 1) ss += __shfl_xor_sync(~0u, ss, o);
    __shared__ float sh[8];
    if ((tid & 31) == 0) sh[tid >> 5] = ss;
    __syncthreads();
    if (tid == 0) {
        float t = 0.f;
        #pragma unroll
        for (int i = 0; i < 8; i++) t += sh[i];
        sh[0] = rsqrtf(t);
    }
    __syncthreads();
    float iv = sh[0];
    v0.x*=iv; v0.y*=iv; v0.z*=iv; v0.w*=iv;
    v1.x*=iv; v1.y*=iv; v1.z*=iv; v1.w*=iv;
    float4* dst = (float4*)(g_xn + (size_t)row * Dd);
    dst[tid] = v0; dst[tid + 256] = v1;
    uint2* bdst = (uint2*)(g_xnb + (size_t)row * Dd);
    bdst[tid]       = make_uint2(pack2(v0.x, v0.y), pack2(v0.z, v0.w));
    bdst[tid + 256] = make_uint2(pack2(v1.x, v1.y), pack2(v1.z, v1.w));
}

// ---------------- K2: prototype stats ----------------
__global__ void k_prep(const float* __restrict__ proto) {
    int b = blockIdx.x, tid = threadIdx.x;
    const float4* pr = (const float4*)(proto + (size_t)b * Pp);
    float mx = -1e30f, sm = 0.f;
    #pragma unroll 4
    for (int i = tid; i < Pp / 4; i += 256) {
        float4 v = pr[i];
        sm += (v.x + v.y) + (v.z + v.w);
        mx = fmaxf(fmaxf(fmaxf(v.x, v.y), fmaxf(v.z, v.w)), mx);
    }
    __shared__ float rm[256], rs[256];
    rm[tid] = mx; rs[tid] = sm;
    __syncthreads();
    for (int o = 128; o; o >>= 1) {
        if (tid < o) { rm[tid] = fmaxf(rm[tid], rm[tid+o]); rs[tid] += rs[tid+o]; }
        __syncthreads();
    }
    float M = fmaxf(rm[0] * TINV, 21.f), S = rs[0] * TINV;
    __syncthreads();
    float se = 0.f;
    for (int i = tid; i < Pp / 4; i += 256) {
        float4 v = pr[i];
        if (fmaxf(fmaxf(v.x, v.y), fmaxf(v.z, v.w)) * TINV > M - 30.f) {
            se += __expf(v.x*TINV - M) + __expf(v.y*TINV - M)
                + __expf(v.z*TINV - M) + __expf(v.w*TINV - M);
        }
    }
    rs[tid] = se;
    __syncthreads();
    for (int o = 128; o; o >>= 1) {
        if (tid < o) rs[tid] += rs[tid+o];
        __syncthreads();
    }
    if (tid == 0) { g_M[b] = M; g_szp[b] = S; g_sep[b] = rs[0]; }
}

// ---------------- K3: exact fp32 target logit ----------------
__global__ void k_target(const float* __restrict__ F, const int* __restrict__ tg) {
    int b = blockIdx.x, tid = threadIdx.x;
    const float4* f = (const float4*)(F + (size_t)tg[b] * Dd);
    const float4* x = (const float4*)(g_xn + (size_t)b * Dd);
    float d = 0.f;
    for (int i = tid; i < Dd / 4; i += 256) {
        float4 a = x[i], c = f[i];
        d += a.x*c.x + a.y*c.y + a.z*c.z + a.w*c.w;
    }
    #pragma unroll
    for (int o = 16; o; o >>= 1) d += __shfl_xor_sync(~0u, d, o);
    __shared__ float sh[8];
    if ((tid & 31) == 0) sh[tid >> 5] = d;
    __syncthreads();
    if (tid == 0) {
        float t = 0.f;
        #pragma unroll
        for (int i = 0; i < 8; i++) t += sh[i];
        g_zt[b] = t * TINV;
    }
}

// ---------------- K4: TMA + ldmatrix bf16 GEMM, pipelined convert ----------
// CTA tile 256(M) x 128(N), stage k=64; 256 threads, 8 warps 4(m) x 2(n).
// Per iter: issue MMAs for stage s FIRST, then convert stage s+1's B while
// the tensor pipe drains; ONE __syncthreads; then TMA-refill slot s.
__global__ void __launch_bounds__(256, 1) k_gemm(
    const __grid_constant__ CUtensorMap tmA,
    const __grid_constant__ CUtensorMap tmB) {
    extern __shared__ char dsm[];
    __shared__ __align__(8) uint64_t s_bar[2];   // full[0..1]

    int tid = threadIdx.x, lane = tid & 31, wid = tid >> 5;
    int wm = wid >> 1, wn = wid & 1;
    int n0 = blockIdx.x * BNg;
    uint32_t sb = (cvs(dsm) + 1023u) & ~1023u;
    uint32_t fullb = cvs(s_bar);

    if (tid == 0) {
        mbar_init(fullb + 0, 1);
        mbar_init(fullb + 8, 1);
    }
    __syncthreads();
    if (tid == 0) {
        #pragma unroll
        for (int p = 0; p < NSTG; p++) {
            mbar_expect(fullb + 8*p, A_BY + BF_BY);
            tma2d(sb + p*STG_BY,                &tmA, p*KC,      0,  fullb + 8*p);
            tma2d(sb + p*STG_BY + A_BY,         &tmB, p*KC,      n0, fullb + 8*p);
            tma2d(sb + p*STG_BY + A_BY + 16384, &tmB, p*KC + 32, n0, fullb + 8*p);
        }
    }

    // ---- conversion geometry: thread -> (n row, k chunk) ----
    int cn = tid >> 1, cc = tid & 1;
    uint32_t Xc = (uint32_t)(cn & 7) << 4;
    uint32_t csrc = (uint32_t)(A_BY + cc * 16384 + cn * 128);
    uint32_t cdst = (uint32_t)(A_BY + BF_BY + cn * 128);
    uint32_t cdo  = (uint32_t)cc * 64u;

    // ---- ldmatrix lane geometry ----
    int l15 = lane & 15;
    uint32_t aHi = (uint32_t)(lane >> 4) << 4;
    uint32_t rowAddrA[4], Xa[4];
    #pragma unroll
    for (int mt = 0; mt < 4; mt++) {
        int row = wm*64 + mt*16 + l15;
        rowAddrA[mt] = (uint32_t)row * 128u;
        Xa[mt] = (uint32_t)(row & 7) << 4;
    }
    int j = lane >> 3;
    uint32_t bCol = (uint32_t)(j & 1) << 4;
    uint32_t rowAddrB[4], Xb[4];
    #pragma unroll
    for (int u = 0; u < 4; u++) {
        int row = wn*64 + u*16 + (lane & 7) + (j >> 1) * 8;
        rowAddrB[u] = (uint32_t)(A_BY + BF_BY) + (uint32_t)row * 128u;
        Xb[u] = (uint32_t)(row & 7) << 4;
    }

    float c[4][8][4];
    #pragma unroll
    for (int i = 0; i < 4; i++)
        #pragma unroll
        for (int jj = 0; jj < 8; jj++)
            #pragma unroll
            for (int k = 0; k < 4; k++) c[i][jj][k] = 0.f;

    // ---- prologue: wait stage 0, convert its B, sync ----
    mbar_wait(fullb + 0, 0);
    {
        uint32_t srcb = sb + csrc;
        uint32_t dstb = sb + cdst;
        #pragma unroll
        for (int j2 = 0; j2 < 4; j2++) {
            float4 lo, hi;
            asm volatile("ld.shared.v4.f32 {%0,%1,%2,%3}, [%4];"
                : "=f"(lo.x), "=f"(lo.y), "=f"(lo.z), "=f"(lo.w)
                : "r"(srcb + (((uint32_t)(2*j2) * 16u) ^ Xc)));
            asm volatile("ld.shared.v4.f32 {%0,%1,%2,%3}, [%4];"
                : "=f"(hi.x), "=f"(hi.y), "=f"(hi.z), "=f"(hi.w)
                : "r"(srcb + (((uint32_t)(2*j2+1) * 16u) ^ Xc)));
            uint32_t p0 = pack2(lo.x, lo.y), p1 = pack2(lo.z, lo.w);
            uint32_t p2 = pack2(hi.x, hi.y), p3 = pack2(hi.z, hi.w);
            asm volatile("st.shared.v4.b32 [%0], {%1,%2,%3,%4};"
                :: "r"(dstb + ((cdo + (uint32_t)j2 * 16u) ^ Xc)),
                   "r"(p0), "r"(p1), "r"(p2), "r"(p3) : "memory");
        }
    }
    __syncthreads();

    for (int it = 0; it < NIT; it++) {
        int s = it & 1, nx = s ^ 1;
        uint32_t sbase = sb + s * STG_BY;

        // ---- 1) issue compute for stage it (fills the tensor queue) ----
        #pragma unroll
        for (int s4 = 0; s4 < 4; s4++) {
            uint32_t kb = (uint32_t)s4 * 32u;
            uint32_t a[4][4], bfr[4][4];
            #pragma unroll
            for (int mt = 0; mt < 4; mt++)
                ldsm4(a[mt][0], a[mt][1], a[mt][2], a[mt][3],
                      sbase + rowAddrA[mt] + ((kb + aHi) ^ Xa[mt]));
            #pragma unroll
            for (int u = 0; u < 4; u++)
                ldsm4(bfr[u][0], bfr[u][1], bfr[u][2], bfr[u][3],
                      sbase + rowAddrB[u] + ((kb + bCol) ^ Xb[u]));
            #pragma unroll
            for (int mt = 0; mt < 4; mt++)
                #pragma unroll
                for (int u = 0; u < 4; u++) {
                    mma16(c[mt][2*u],     a[mt], bfr[u][0], bfr[u][1]);
                    mma16(c[mt][2*u + 1], a[mt], bfr[u][2], bfr[u][3]);
                }
        }

        // ---- 2) overlap: wait TMA of stage it+1, convert its B ----
        if (it + 1 < NIT) {
            mbar_wait(fullb + 8*nx, (uint32_t)(((it + 1) >> 1) & 1));
            uint32_t srcb = sb + nx * STG_BY + csrc;
            uint32_t dstb = sb + nx * STG_BY + cdst;
            #pragma unroll
            for (int j2 = 0; j2 < 4; j2++) {
                float4 lo, hi;
                asm volatile("ld.shared.v4.f32 {%0,%1,%2,%3}, [%4];"
                    : "=f"(lo.x), "=f"(lo.y), "=f"(lo.z), "=f"(lo.w)
                    : "r"(srcb + (((uint32_t)(2*j2) * 16u) ^ Xc)));
                asm volatile("ld.shared.v4.f32 {%0,%1,%2,%3}, [%4];"
                    : "=f"(hi.x), "=f"(hi.y), "=f"(hi.z), "=f"(hi.w)
                    : "r"(srcb + (((uint32_t)(2*j2+1) * 16u) ^ Xc)));
                uint32_t p0 = pack2(lo.x, lo.y), p1 = pack2(lo.z, lo.w);
                uint32_t p2 = pack2(hi.x, hi.y), p3 = pack2(hi.z, hi.w);
                asm volatile("st.shared.v4.b32 [%0], {%1,%2,%3,%4};"
                    :: "r"(dstb + ((cdo + (uint32_t)j2 * 16u) ^ Xc)),
                       "r"(p0), "r"(p1), "r"(p2), "r"(p3) : "memory");
            }
        }

        // ---- 3) single barrier: compute(s) reads done, convert(nx) visible --
        __syncthreads();

        // ---- 4) refill slot s with stage it+2 ----
        if (tid == 0 && it + 2 < NIT) {
            int k0 = (it + 2) * KC;
            mbar_expect(fullb + 8*s, A_BY + BF_BY);
            tma2d(sbase,                &tmA, k0,      0,  fullb + 8*s);
            tma2d(sbase + A_BY,         &tmB, k0,      n0, fullb + 8*s);
            tma2d(sbase + A_BY + 16384, &tmB, k0 + 32, n0, fullb + 8*s);
        }
    }
    __syncthreads();

    // ---- fused epilogue: per-row sum + softmax numerator partials ----
    int g = lane >> 2, q = lane & 3;
    float* redv = (float*)dsm;          // [2 wn][256 rows]
    float* rede = redv + 512;
    #pragma unroll
    for (int mt = 0; mt < 4; mt++) {
        int r0 = wm*64 + mt*16 + g;
        float M0 = g_M[r0], M1 = g_M[r0 + 8];
        float sv0 = 0.f, se0 = 0.f, sv1 = 0.f, se1 = 0.f;
        #pragma unroll
        for (int nt = 0; nt < 8; nt++) {
            float v;
            v = c[mt][nt][0]; sv0 += v; se0 += __expf(fmaf(TINV, v, -M0));
            v = c[mt][nt][1]; sv0 += v; se0 += __expf(fmaf(TINV, v, -M0));
            v = c[mt][nt][2]; sv1 += v; se1 += __expf(fmaf(TINV, v, -M1));
            v = c[mt][nt][3]; sv1 += v; se1 += __expf(fmaf(TINV, v, -M1));
        }
        #pragma unroll
        for (int o = 1; o <= 2; o <<= 1) {
            sv0 += __shfl_xor_sync(~0u, sv0, o);
            se0 += __shfl_xor_sync(~0u, se0, o);
            sv1 += __shfl_xor_sync(~0u, sv1, o);
            se1 += __shfl_xor_sync(~0u, se1, o);
        }
        if (q == 0) {
            redv[wn*256 + r0]     = sv0; rede[wn*256 + r0]     = se0;
            redv[wn*256 + r0 + 8] = sv1; rede[wn*256 + r0 + 8] = se1;
        }
    }
    __syncthreads();
    {
        float sv = redv[tid] + redv[256 + tid];
        float se = rede[tid] + rede[256 + tid];
        g_psv[(size_t)tid * NBLK + blockIdx.x] = sv;
        g_pse[(size_t)tid * NBLK + blockIdx.x] = se;
    }
}

// ---------------- K5: per-row combine over 512 CTA partials ----------------
__global__ void k_finalrow(void) {
    int b = blockIdx.x, tid = threadIdx.x;
    float sv = g_psv[(size_t)b * NBLK + tid] + g_psv[(size_t)b * NBLK + tid + 256];
    float se = g_pse[(size_t)b * NBLK + tid] + g_pse[(size_t)b * NBLK + tid + 256];
    __shared__ float rv[256], re[256];
    rv[tid] = sv; re[tid] = se;
    __syncthreads();
    for (int o = 128; o; o >>= 1) {
        if (tid < o) { rv[tid] += rv[tid+o]; re[tid] += re[tid+o]; }
        __syncthreads();
    }
    if (tid == 0) {
        float M = g_M[b];
        float lse = M + logf(g_sep[b] + re[0]);
        float T = g_szp[b] + TINV * rv[0];
        g_rowloss[b] = lse - (1.f - EPS_) * g_zt[b] - EPS_ * (T / (float)CTOT);
    }
}

// ---------------- K6: mean ----------------
__global__ void k_final(float* __restrict__ out) {
    int tid = threadIdx.x;
    float v = g_rowloss[tid];
    #pragma unroll
    for (int o = 16; o; o >>= 1) v += __shfl_xor_sync(~0u, v, o);
    __shared__ float sh[8];
    if ((tid & 31) == 0) sh[tid >> 5] = v;
    __syncthreads();
    if (tid == 0) {
        float s = 0.f;
        #pragma unroll
        for (int i = 0; i < 8; i++) s += sh[i];
        out[0] = s / (float)Bb;
    }
}

// ---------------------------------------------------------------------------
typedef CUresult (*PFN_tmapenc)(
    CUtensorMap*, CUtensorMapDataType, cuuint32_t, void*,
    const cuuint64_t*, const cuuint64_t*, const cuuint32_t*, const cuuint32_t*,
    CUtensorMapInterleave, CUtensorMapSwizzle, CUtensorMapL2promotion,
    CUtensorMapFloatOOBfill);

extern "C" void kernel_launch(void* const* d_in, const int* in_sizes, int n_in,
                              void* d_out, int out_size) {
    const float* inputs    = (const float*)d_in[0];
    const int*   targets   = (const int*)  d_in[1];
    const float* prototype = (const float*)d_in[2];
    const float* features  = (const float*)d_in[3];
    float* out = (float*)d_out;

    cudaFuncSetAttribute(k_gemm, cudaFuncAttributeMaxDynamicSharedMemorySize,
                         SMEM_DYN);

    PFN_tmapenc enc = nullptr;
    cudaDriverEntryPointQueryResult qr;
    cudaGetDriverEntryPointByVersion("cuTensorMapEncodeTiled", (void**)&enc,
                                     12000, cudaEnableDefault, &qr);

    void* xnbp = nullptr;
    cudaGetSymbolAddress(&xnbp, g_xnb);

    CUtensorMap tmA, tmB;
    {
        cuuint64_t dims[2]    = {Dd, Bb};
        cuuint64_t strides[1] = {Dd * 2ull};
        cuuint32_t box[2]     = {KC, Bb};          // 64 bf16 = 128 B x 256 rows
        cuuint32_t es[2]      = {1, 1};
        enc(&tmA, CU_TENSOR_MAP_DATA_TYPE_BFLOAT16, 2, xnbp, dims, strides, box, es,
            CU_TENSOR_MAP_INTERLEAVE_NONE, CU_TENSOR_MAP_SWIZZLE_128B,
            CU_TENSOR_MAP_L2_PROMOTION_L2_128B, CU_TENSOR_MAP_FLOAT_OOB_FILL_NONE);
    }
    {
        cuuint64_t dims[2]    = {Dd, Nn};
        cuuint64_t strides[1] = {Dd * 4ull};
        cuuint32_t box[2]     = {32, BNg};         // 32 f32 = 128 B x 128 rows
        cuuint32_t es[2]      = {1, 1};
        enc(&tmB, CU_TENSOR_MAP_DATA_TYPE_FLOAT32, 2, (void*)features,
            dims, strides, box, es,
            CU_TENSOR_MAP_INTERLEAVE_NONE, CU_TENSOR_MAP_SWIZZLE_128B,
            CU_TENSOR_MAP_L2_PROMOTION_L2_128B, CU_TENSOR_MAP_FLOAT_OOB_FILL_NONE);
    }

    k_normalize<<<Bb, 256>>>(inputs);
    k_prep<<<Bb, 256>>>(prototype);
    k_target<<<Bb, 256>>>(features, targets);
    k_gemm<<<NBLK, 256, SMEM_DYN>>>(tmA, tmB);
    k_finalrow<<<Bb, 256>>>();
    k_final<<<1, 256>>>(out);
}